// round 15
// baseline (speedup 1.0000x reference)
#include <cuda_runtime.h>
#include <cstdint>
#include <math.h>

// poses: (4096, 3, 128, 17) float32, channel 1 used.
// out:   [ma(7,4096); mi(7,4096)] stored as float32.
//
// One 32-thread block per batch (grid 4096), cp.async staged in TWO commit
// groups: A = chunks 0..8 (floats 0..1151, covers frames 0..63),
// B = chunks 9..16. wait_group 1 -> compute frames lane, lane+32 while B is
// in flight; wait_group 0 -> frames lane+64, lane+96. Arithmetic identical
// to the 8.9us kernel (rcp.approx, FMA-fused transform, 1-divide epilogue,
// REDUX reduction).

#define NB 4096
#define FRAMES 128
#define JOINTS 17
#define ROW_F (FRAMES * JOINTS)   // 2176 floats; 8704 B slice, 16B-aligned

__device__ __forceinline__ int f2o(float f) {
    int b = __float_as_int(f);
    return b ^ ((b >> 31) & 0x7fffffff);
}
__device__ __forceinline__ float o2f(int k) {
    return __int_as_float(k ^ ((k >> 31) & 0x7fffffff));
}
__device__ __forceinline__ float warp_max_f32(float v) {
    return o2f(__reduce_max_sync(0xffffffffu, f2o(v)));
}
__device__ __forceinline__ float warp_min_f32(float v) {
    return o2f(__reduce_min_sync(0xffffffffu, f2o(v)));
}
__device__ __forceinline__ float rcp_approx(float x) {
    float r; asm("rcp.approx.f32 %0, %1;" : "=f"(r) : "f"(x)); return r;
}

__device__ __forceinline__ void do_frame(const float* __restrict__ row, float* __restrict__ r)
{
    float x[JOINTS];
    #pragma unroll
    for (int j = 0; j < JOINTS; j++) x[j] = row[j];

    const float x0 = x[0];
    const float ratio = __fmul_rn(__fadd_rn(__fsub_rn(x[5], x0), __fsub_rn(x[6], x0)), 0.5f);
    const float rcp = rcp_approx(ratio);
    const float nb0 = __fmul_rn(-x0, rcp);     // -x0*rcp

    float v[JOINTS];
    v[0] = 0.0f;                               // (x0-x0)/ratio == 0 exactly
    #pragma unroll
    for (int j = 1; j < JOINTS; j++)
        v[j] = __fmaf_rn(x[j], rcp, nb0);      // (x - x0)*rcp, fused

    float pmax[7], pmin[7];
    #pragma unroll
    for (int p = 0; p < 7; p++) { pmax[p] = -INFINITY; pmin[p] = INFINITY; }
    #pragma unroll
    for (int j = 0; j < JOINTS; j++) {
        const int p = (j < 5) ? 0 : ((j - 3) >> 1);
        pmax[p] = fmaxf(pmax[p], v[j]);
        pmin[p] = fminf(pmin[p], v[j]);
    }
    float fm = pmin[0];
    #pragma unroll
    for (int p = 1; p < 7; p++) fm = fminf(fm, pmin[p]);
    // max/min commute with the monotone subtraction of fm
    #pragma unroll
    for (int p = 0; p < 7; p++) {
        r[p]     = fmaxf(r[p],     __fsub_rn(pmax[p], fm));
        r[p + 7] = fminf(r[p + 7], __fsub_rn(pmin[p], fm));
    }
}

__global__ __launch_bounds__(32) void divid_part_kernel(
    const float* __restrict__ poses, float* __restrict__ out)
{
    __shared__ __align__(16) float s[ROW_F];

    const int lane = threadIdx.x;
    const int b    = blockIdx.x;

    const float4* g4 = reinterpret_cast<const float4*>(poses + ((size_t)b * 3 + 1) * ROW_F);
    unsigned int sbase;
    asm("{ .reg .u64 t; cvta.to.shared.u64 t, %1; cvt.u32.u64 %0, t; }"
        : "=r"(sbase) : "l"(&s[0]));

    // Group A: chunks 0..8 (floats 0..1151; frames 0..63 need <= float 1087).
    #pragma unroll
    for (int i = 0; i < 9; i++) {
        const int idx = lane + i * 32;
        asm volatile("cp.async.cg.shared.global [%0], [%1], 16;"
                     :: "r"(sbase + idx * 16), "l"(g4 + idx));
    }
    asm volatile("cp.async.commit_group;");
    // Group B: chunks 9..16.
    #pragma unroll
    for (int i = 9; i < 17; i++) {
        const int idx = lane + i * 32;
        asm volatile("cp.async.cg.shared.global [%0], [%1], 16;"
                     :: "r"(sbase + idx * 16), "l"(g4 + idx));
    }
    asm volatile("cp.async.commit_group;");

    float r[14];
    #pragma unroll
    for (int k = 0; k < 7; k++) { r[k] = -INFINITY; r[k + 7] = INFINITY; }

    // Wait for A only; compute frames lane, lane+32 while B is in flight.
    asm volatile("cp.async.wait_group 1;");
    __syncwarp();
    do_frame(&s[lane * JOINTS],        r);
    do_frame(&s[(lane + 32) * JOINTS], r);

    // Wait for B; frames lane+64, lane+96.
    asm volatile("cp.async.wait_group 0;");
    __syncwarp();
    do_frame(&s[(lane + 64) * JOINTS], r);
    do_frame(&s[(lane + 96) * JOINTS], r);

    // ---- Warp reduction: 14 integer REDUX ops (broadcast to all lanes).
    #pragma unroll
    for (int k = 0; k < 7; k++) {
        r[k]     = warp_max_f32(r[k]);
        r[k + 7] = warp_min_f32(r[k + 7]);
    }

    float bottom = r[0], top = r[7];
    #pragma unroll
    for (int p = 1; p < 7; p++) {
        bottom = fmaxf(bottom, r[p]);
        top    = fminf(top,    r[p + 7]);
    }
    // ONE divide for the whole epilogue.
    const float inv = __fdiv_rn(64.0f, __fsub_rn(bottom, top));

    int ma_[7], mi_[7];
    #pragma unroll
    for (int p = 0; p < 7; p++) {
        int ma = (int)ceilf (__fmul_rn(__fsub_rn(r[p],     top), inv));
        int mi = (int)floorf(__fmul_rn(__fsub_rn(r[p + 7], top), inv));
        const int hi = (p + 1) * 9, lo = p * 9;
        if (ma <= mi || ma - mi > 30) { ma = hi; mi = lo; }
        ma_[p] = ma; mi_[p] = mi;
    }
    if (lane == 0) {
        #pragma unroll
        for (int p = 0; p < 7; p++) {
            out[p * NB + b]       = (float)ma_[p];
            out[(7 + p) * NB + b] = (float)mi_[p];
        }
    }
}

extern "C" void kernel_launch(void* const* d_in, const int* in_sizes, int n_in,
                              void* d_out, int out_size)
{
    const float* poses = (const float*)d_in[0];
    float* out = (float*)d_out;
    divid_part_kernel<<<NB, 32>>>(poses, out);
}